// round 6
// baseline (speedup 1.0000x reference)
#include <cuda_runtime.h>
#include <math.h>

#define ED    64      // embed dim
#define NKK   32      // w2 output dim
#define N_MAX 2048

// ---------------- device scratch (no allocations allowed) ----------------
// Rows 0..15 = subj, 16..24 = rel, 25..40 = obj. A = hi-side, B = hj-side.
__device__ float g_P[41 * ED];      // projected tables (stage 1)
__device__ float g_Atab[41 * ED];
__device__ float g_Btab[41 * ED];
// Transposed (d-major) per-row features: [d][n]
__device__ float g_HIt[ED * N_MAX];
__device__ float g_HJt[ED * N_MAX];

// ---------------- packed f32x2 helpers (FFMA2 only via PTX) ----------------
__device__ __forceinline__ unsigned long long pack2(float a, float b) {
    unsigned long long r;
    asm("mov.b64 %0, {%1, %2};" : "=l"(r) : "f"(a), "f"(b));
    return r;
}
__device__ __forceinline__ void unpack2(unsigned long long v, float &a, float &b) {
    asm("mov.b64 {%0, %1}, %2;" : "=f"(a), "=f"(b) : "l"(v));
}
__device__ __forceinline__ unsigned long long fma2(unsigned long long a,
                                                   unsigned long long b,
                                                   unsigned long long c) {
    unsigned long long d;
    asm("fma.rn.f32x2 %0, %1, %2, %3;" : "=l"(d) : "l"(a), "l"(b), "l"(c));
    return d;
}

__device__ __forceinline__ float warp_sum(float v) {
#pragma unroll
    for (int s = 16; s; s >>= 1) v += __shfl_xor_sync(0xffffffffu, v, s);
    return v;
}

// ---------------- stage P1: projected tables, one warp per output ----------
// P[row][k] = sum_m table[row][m] * proj_w[k][off+m]
__global__ void p1_kernel(const float* __restrict__ st,
                          const float* __restrict__ rt,
                          const float* __restrict__ ot,
                          const float* __restrict__ pw)   // [64][192]
{
    int warp = (blockIdx.x * blockDim.x + threadIdx.x) >> 5;
    int lane = threadIdx.x & 31;
    if (warp >= 41 * ED) return;
    int row = warp >> 6, k = warp & 63;
    const float* tab;
    int off;
    if (row < 16)      { tab = st + row * ED;        off = 0;   }
    else if (row < 25) { tab = rt + (row - 16) * ED; off = 64;  }
    else               { tab = ot + (row - 25) * ED; off = 128; }
    const float* wrow = pw + k * 192 + off;
    float v = tab[lane] * wrow[lane] + tab[lane + 32] * wrow[lane + 32];
    v = warp_sum(v);
    if (lane == 0) g_P[warp] = v;
}

// ---------------- stage P2: A/B tables, one warp per output ----------------
// A[row][d] = dot(P[row], w1a[d]);  B[row][d] = dot(P[row], w1b[d]).
// Obj rows (>=25) fold in the proj_b-propagated bias; B side also gets b1.
__global__ void p2_kernel(const float* __restrict__ pb,   // [64]
                          const float* __restrict__ w1,   // [64][128]
                          const float* __restrict__ b1)   // [64]
{
    int warp = (blockIdx.x * blockDim.x + threadIdx.x) >> 5;
    int lane = threadIdx.x & 31;
    if (warp >= 2 * 41 * ED) return;
    int side = warp / (41 * ED);
    int rem  = warp % (41 * ED);
    int row = rem >> 6, d = rem & 63;
    const float* w1row = w1 + d * 128 + side * 64;
    const float* Prow  = g_P + row * ED;
    float v = Prow[lane] * w1row[lane] + Prow[lane + 32] * w1row[lane + 32];
    if (row >= 25)
        v += pb[lane] * w1row[lane] + pb[lane + 32] * w1row[lane + 32];
    v = warp_sum(v);
    if (lane == 0) {
        if (row >= 25 && side == 1) v += b1[d];
        if (side) g_Btab[rem] = v;
        else      g_Atab[rem] = v;
    }
}

// ---------------- kernel B: gather -> HI/HJ in d-major layout --------------
__global__ void gather_kernel(const int* __restrict__ si,
                              const int* __restrict__ ri,
                              const int* __restrict__ oi, int n)
{
    int g = blockIdx.x * blockDim.x + threadIdx.x;
    int total = (ED / 4) * n;
    if (g >= total) return;
    int d4 = g / n;        // which group of 4 d's
    int nn = g % n;        // row index (consecutive across lanes -> coalesced)
    int c  = d4 * 4;
    int s = si[nn], r = ri[nn], o = oi[nn];

    float4 a0 = *(const float4*)&g_Atab[s * ED + c];
    float4 a1 = *(const float4*)&g_Atab[(16 + r) * ED + c];
    float4 a2 = *(const float4*)&g_Atab[(25 + o) * ED + c];
    g_HIt[(c + 0) * n + nn] = a0.x + a1.x + a2.x;
    g_HIt[(c + 1) * n + nn] = a0.y + a1.y + a2.y;
    g_HIt[(c + 2) * n + nn] = a0.z + a1.z + a2.z;
    g_HIt[(c + 3) * n + nn] = a0.w + a1.w + a2.w;

    float4 b0 = *(const float4*)&g_Btab[s * ED + c];
    float4 b1v = *(const float4*)&g_Btab[(16 + r) * ED + c];
    float4 b2v = *(const float4*)&g_Btab[(25 + o) * ED + c];
    g_HJt[(c + 0) * n + nn] = b0.x + b1v.x + b2v.x;
    g_HJt[(c + 1) * n + nn] = b0.y + b1v.y + b2v.y;
    g_HJt[(c + 2) * n + nn] = b0.z + b1v.z + b2v.z;
    g_HJt[(c + 3) * n + nn] = b0.w + b1v.w + b2v.w;
}

// ---------------- kernel C: pairwise scores, 32x32 tiles, FFMA2 ------------
// Thread layout: 256 threads = 32 i-rows x 8 j-quads; each thread owns
// (1 i) x (4 j) packed as two f32x2 lanes. k split in two passes of 16 to
// keep the accumulator at 32 x u64 registers.
__global__ void __launch_bounds__(256, 2)
score_kernel(const float* __restrict__ w2,   // [32][64]
             const float* __restrict__ b2,   // [32]
             const float* __restrict__ w3,   // [1][32]
             const float* __restrict__ b3,   // [1]
             float* __restrict__ out, int n)
{
    const int ti = blockIdx.y, tj = blockIdx.x;
    const int t  = threadIdx.x;
    const int il = t >> 3;          // local i row 0..31
    const int jq = t & 7;           // j quad 0..7
    const int i0 = ti * 32, j0 = tj * 32;

    if (tj < ti) {  // entire tile strictly below diagonal -> zeros only
        *(float4*)&out[(size_t)(i0 + il) * n + j0 + jq * 4] =
            make_float4(0.f, 0.f, 0.f, 0.f);
        return;
    }

    __shared__ __align__(16) float  sHI[ED][32];     // [d][i]
    __shared__ __align__(16) float  sHJ[ED][32];     // [d][j]
    __shared__ __align__(16) float2 sW2[ED][NKK];    // [d][k], duplicated (w,w)
    __shared__ float sw3[NKK], sb2[NKK];

#pragma unroll
    for (int r = 0; r < 2; r++) {                    // 512 float4s, 2/thread
        int idx = r * 256 + t;
        int row = idx >> 3, c4 = (idx & 7) * 4;
        *(float4*)&sHI[row][c4] = *(const float4*)&g_HIt[row * n + i0 + c4];
        *(float4*)&sHJ[row][c4] = *(const float4*)&g_HJt[row * n + j0 + c4];
    }
#pragma unroll
    for (int r = 0; r < 8; r++) {                    // 2048 w2 elems, 8/thread
        int idx = r * 256 + t;
        int d = idx >> 5, k = idx & 31;
        float w = w2[k * ED + d];
        sW2[d][k] = make_float2(w, w);
    }
    if (t < NKK) { sw3[t] = w3[t]; sb2[t] = b2[t]; }
    __syncthreads();

    float s0 = 0.f, s1 = 0.f, s2 = 0.f, s3 = 0.f;

#pragma unroll
    for (int pass = 0; pass < 2; pass++) {
        const int kb = pass * 16;
        unsigned long long acc0[16], acc1[16];
#pragma unroll
        for (int k = 0; k < 16; k++) { acc0[k] = 0ull; acc1[k] = 0ull; }

#pragma unroll 4
        for (int d = 0; d < ED; d++) {
            float  hi  = sHI[d][il];
            float4 hj4 = *(const float4*)&sHJ[d][jq * 4];
            float h0 = fmaxf(hi + hj4.x, 0.f);
            float h1 = fmaxf(hi + hj4.y, 0.f);
            float h2 = fmaxf(hi + hj4.z, 0.f);
            float h3 = fmaxf(hi + hj4.w, 0.f);
            unsigned long long H01 = pack2(h0, h1);
            unsigned long long H23 = pack2(h2, h3);
#pragma unroll
            for (int k = 0; k < 16; k++) {
                unsigned long long w =
                    *(const unsigned long long*)&sW2[d][kb + k];
                acc0[k] = fma2(H01, w, acc0[k]);
                acc1[k] = fma2(H23, w, acc1[k]);
            }
        }

#pragma unroll
        for (int k = 0; k < 16; k++) {
            float a0, a1, a2, a3;
            unpack2(acc0[k], a0, a1);
            unpack2(acc1[k], a2, a3);
            float bb = sb2[kb + k], ww = sw3[kb + k];
            s0 += fmaxf(a0 + bb, 0.f) * ww;
            s1 += fmaxf(a1 + bb, 0.f) * ww;
            s2 += fmaxf(a2 + bb, 0.f) * ww;
            s3 += fmaxf(a3 + bb, 0.f) * ww;
        }
    }

    const float bb3 = b3[0];
    const int i  = i0 + il;
    const int jb = j0 + jq * 4;
    float4 r;
    r.x = (jb + 0 > i) ? 1.f / (1.f + __expf(-(s0 + bb3))) : 0.f;
    r.y = (jb + 1 > i) ? 1.f / (1.f + __expf(-(s1 + bb3))) : 0.f;
    r.z = (jb + 2 > i) ? 1.f / (1.f + __expf(-(s2 + bb3))) : 0.f;
    r.w = (jb + 3 > i) ? 1.f / (1.f + __expf(-(s3 + bb3))) : 0.f;
    *(float4*)&out[(size_t)i * n + jb] = r;
}

// ---------------- launch ----------------------------------------------------
extern "C" void kernel_launch(void* const* d_in, const int* in_sizes, int n_in,
                              void* d_out, int out_size)
{
    const int*   si = (const int*)d_in[0];
    const int*   ri = (const int*)d_in[1];
    const int*   oi = (const int*)d_in[2];
    const float* st = (const float*)d_in[3];
    const float* rt = (const float*)d_in[4];
    const float* ot = (const float*)d_in[5];
    const float* pw = (const float*)d_in[6];
    const float* pb = (const float*)d_in[7];
    const float* w1 = (const float*)d_in[8];
    const float* b1 = (const float*)d_in[9];
    const float* w2 = (const float*)d_in[10];
    const float* b2 = (const float*)d_in[11];
    const float* w3 = (const float*)d_in[12];
    const float* b3 = (const float*)d_in[13];
    float* out = (float*)d_out;
    const int n = in_sizes[0];

    // P1: one warp per projected-table element (41*64 outputs)
    p1_kernel<<<(41 * ED * 32 + 255) / 256, 256>>>(st, rt, ot, pw);
    // P2: one warp per A/B-table element (2*41*64 outputs)
    p2_kernel<<<(2 * 41 * ED * 32 + 255) / 256, 256>>>(pb, w1, b1);

    int total = (ED / 4) * n;
    gather_kernel<<<(total + 255) / 256, 256>>>(si, ri, oi, n);

    dim3 grid(n / 32, n / 32);
    score_kernel<<<grid, 256>>>(w2, b2, w3, b3, out, n);
}

// round 8
// speedup vs baseline: 3.2515x; 3.2515x over previous
#include <cuda_runtime.h>
#include <cuda_bf16.h>
#include <math.h>
#include <cstdint>

#define ED    64      // embed dim
#define NKK   32      // w2 output dim
#define N_MAX 2048

// ---------------- device scratch (no allocations allowed) ----------------
// Rows 0..15 = subj, 16..24 = rel, 25..40 = obj. A = hi-side, B = hj-side.
__device__ float g_P[41 * ED];      // projected tables (stage 1)
__device__ float g_Atab[41 * ED];
__device__ float g_Btab[41 * ED];
// Row-major per-row features: [n][d]
__device__ float g_HI[N_MAX * ED];
__device__ float g_HJ[N_MAX * ED];

__device__ __forceinline__ float warp_sum(float v) {
#pragma unroll
    for (int s = 16; s; s >>= 1) v += __shfl_xor_sync(0xffffffffu, v, s);
    return v;
}

// relu + pack two f32 into bf16x2 (lo = first elem). relu after cvt == cvt of
// relu (monotone, cvt(0)=0), done on the packed pair with max.bf16x2.
__device__ __forceinline__ uint32_t bf2_relu(float lo, float hi) {
    uint32_t r;
    asm("cvt.rn.bf16x2.f32 %0, %1, %2;" : "=r"(r) : "f"(hi), "f"(lo));
    asm("max.bf16x2 %0, %0, %1;" : "+r"(r) : "r"(0u));
    return r;
}
__device__ __forceinline__ uint32_t bf2(float lo, float hi) {
    uint32_t r;
    asm("cvt.rn.bf16x2.f32 %0, %1, %2;" : "=r"(r) : "f"(hi), "f"(lo));
    return r;
}

// ---------------- stage P1: projected tables, one warp per output ----------
__global__ void p1_kernel(const float* __restrict__ st,
                          const float* __restrict__ rt,
                          const float* __restrict__ ot,
                          const float* __restrict__ pw)   // [64][192]
{
    int warp = (blockIdx.x * blockDim.x + threadIdx.x) >> 5;
    int lane = threadIdx.x & 31;
    if (warp >= 41 * ED) return;
    int row = warp >> 6, k = warp & 63;
    const float* tab;
    int off;
    if (row < 16)      { tab = st + row * ED;        off = 0;   }
    else if (row < 25) { tab = rt + (row - 16) * ED; off = 64;  }
    else               { tab = ot + (row - 25) * ED; off = 128; }
    const float* wrow = pw + k * 192 + off;
    float v = tab[lane] * wrow[lane] + tab[lane + 32] * wrow[lane + 32];
    v = warp_sum(v);
    if (lane == 0) g_P[warp] = v;
}

// ---------------- stage P2: A/B tables, one warp per output ----------------
__global__ void p2_kernel(const float* __restrict__ pb,   // [64]
                          const float* __restrict__ w1,   // [64][128]
                          const float* __restrict__ b1)   // [64]
{
    int warp = (blockIdx.x * blockDim.x + threadIdx.x) >> 5;
    int lane = threadIdx.x & 31;
    if (warp >= 2 * 41 * ED) return;
    int side = warp / (41 * ED);
    int rem  = warp % (41 * ED);
    int row = rem >> 6, d = rem & 63;
    const float* w1row = w1 + d * 128 + side * 64;
    const float* Prow  = g_P + row * ED;
    float v = Prow[lane] * w1row[lane] + Prow[lane + 32] * w1row[lane + 32];
    if (row >= 25)
        v += pb[lane] * w1row[lane] + pb[lane + 32] * w1row[lane + 32];
    v = warp_sum(v);
    if (lane == 0) {
        if (row >= 25 && side == 1) v += b1[d];
        if (side) g_Btab[rem] = v;
        else      g_Atab[rem] = v;
    }
}

// ---------------- gather -> HI/HJ in row-major [n][d] layout ---------------
__global__ void gather_kernel(const int* __restrict__ si,
                              const int* __restrict__ ri,
                              const int* __restrict__ oi, int n)
{
    int g = blockIdx.x * blockDim.x + threadIdx.x;
    if (g >= n * (ED / 4)) return;
    int nn = g >> 4;
    int c  = (g & 15) * 4;
    int s = si[nn], r = ri[nn], o = oi[nn];

    float4 a0 = *(const float4*)&g_Atab[s * ED + c];
    float4 a1 = *(const float4*)&g_Atab[(16 + r) * ED + c];
    float4 a2 = *(const float4*)&g_Atab[(25 + o) * ED + c];
    *(float4*)&g_HI[nn * ED + c] =
        make_float4(a0.x + a1.x + a2.x, a0.y + a1.y + a2.y,
                    a0.z + a1.z + a2.z, a0.w + a1.w + a2.w);

    float4 b0 = *(const float4*)&g_Btab[s * ED + c];
    float4 b1v = *(const float4*)&g_Btab[(16 + r) * ED + c];
    float4 b2v = *(const float4*)&g_Btab[(25 + o) * ED + c];
    *(float4*)&g_HJ[nn * ED + c] =
        make_float4(b0.x + b1v.x + b2v.x, b0.y + b1v.y + b2v.y,
                    b0.z + b1v.z + b2v.z, b0.w + b1v.w + b2v.w);
}

// ---------------- score kernel: mma.sync bf16 tensor path ------------------
// CTA tile = 64 i x 32 j. Warp w owns i-rows w*8..w*8+7. One m16 MMA tile =
// one i x 16 j's (j maps to MMA M-rows, k_out to N, d to K).
//   D[j][k] = sum_d relu(hi[i][d] + hj[j][d]) * w2[k][d]
// A fragments built in registers from SMEM (hi broadcast + transposed hj),
// B fragments (w2) and b2/w3 preloaded in registers.
#define TI 64
#define TJ 32
#define SJ 36   // hjT row stride (floats): bank = 8c+g, conflict-free

__global__ void __launch_bounds__(256)
score_kernel(const float* __restrict__ w2,   // [32][64]
             const float* __restrict__ b2,   // [32]
             const float* __restrict__ w3,   // [1][32]
             const float* __restrict__ b3,   // [1]
             float* __restrict__ out, int n)
{
    const int t = threadIdx.x, w = t >> 5, lane = t & 31;
    const int gr = lane >> 2, c = lane & 3;
    const int i0 = blockIdx.y * TI, j0 = blockIdx.x * TJ;

    // Tile entirely at/below diagonal -> pure zeros.
    if (j0 + TJ - 1 <= i0) {
        const float4 z = make_float4(0.f, 0.f, 0.f, 0.f);
#pragma unroll
        for (int q = 0; q < 2; q++) {
            int idx = q * 256 + t;
            int r = idx >> 3, f4 = (idx & 7) * 4;
            *(float4*)&out[(size_t)(i0 + r) * n + j0 + f4] = z;
        }
        return;
    }

    __shared__ __align__(16) float sHI[TI * ED];      // [i][d], 16KB
    __shared__ float sHJT[ED * SJ];                   // [d][j], 9KB

    // Stage hi rows (coalesced float4).
#pragma unroll
    for (int q = 0; q < 4; q++) {
        int idx = q * 256 + t;
        int r = idx >> 4, c4 = (idx & 15) * 4;
        *(float4*)&sHI[r * ED + c4] = *(const float4*)&g_HI[(i0 + r) * ED + c4];
    }
    // Stage hj transposed: sHJT[d][j] = g_HJ[j0+j][d].
#pragma unroll
    for (int q = 0; q < 2; q++) {
        int idx = q * 256 + t;
        int j = idx >> 4, d4 = (idx & 15) * 4;
        float4 v = *(const float4*)&g_HJ[(j0 + j) * ED + d4];
        sHJT[(d4 + 0) * SJ + j] = v.x;
        sHJT[(d4 + 1) * SJ + j] = v.y;
        sHJT[(d4 + 2) * SJ + j] = v.z;
        sHJT[(d4 + 3) * SJ + j] = v.w;
    }

    // Preload B fragments: Bf[kt][nt][r]; b0 = w2[n][dk], w2[n][dk+1] with
    // n = nt*8+gr, dk = kt*16+2c; b1 = same at dk+8.
    uint32_t Bf[4][4][2];
#pragma unroll
    for (int kt = 0; kt < 4; kt++)
#pragma unroll
        for (int nt = 0; nt < 4; nt++) {
            const float* wrow = w2 + (nt * 8 + gr) * ED + kt * 16 + 2 * c;
            float2 wa = *(const float2*)&wrow[0];
            float2 wb = *(const float2*)&wrow[8];
            Bf[kt][nt][0] = bf2(wa.x, wa.y);
            Bf[kt][nt][1] = bf2(wb.x, wb.y);
        }
    // Per-thread epilogue constants for cols nt*8 + 2c, +1.
    float b2v[8], w3v[8];
#pragma unroll
    for (int nt = 0; nt < 4; nt++) {
        float2 bb = *(const float2*)&b2[nt * 8 + 2 * c];
        float2 ww = *(const float2*)&w3[nt * 8 + 2 * c];
        b2v[nt * 2] = bb.x; b2v[nt * 2 + 1] = bb.y;
        w3v[nt * 2] = ww.x; w3v[nt * 2 + 1] = ww.y;
    }
    const float b3v = b3[0];
    __syncthreads();

#pragma unroll 1
    for (int il = 0; il < 8; il++) {
        const int i = i0 + w * 8 + il;
        const float* hiRow = sHI + (w * 8 + il) * ED;
#pragma unroll
        for (int jt = 0; jt < 2; jt++) {
            float cr[4][4];
#pragma unroll
            for (int nt = 0; nt < 4; nt++)
#pragma unroll
                for (int r = 0; r < 4; r++) cr[nt][r] = 0.f;

            const int jb = jt * 16 + gr;
#pragma unroll
            for (int kt = 0; kt < 4; kt++) {
                const int d0 = kt * 16 + 2 * c;
                float2 hi0 = *(const float2*)&hiRow[d0];
                float2 hi1 = *(const float2*)&hiRow[d0 + 8];
                float x0 = sHJT[(d0 + 0) * SJ + jb];
                float x1 = sHJT[(d0 + 1) * SJ + jb];
                float x2 = sHJT[(d0 + 0) * SJ + jb + 8];
                float x3 = sHJT[(d0 + 1) * SJ + jb + 8];
                float x4 = sHJT[(d0 + 8) * SJ + jb];
                float x5 = sHJT[(d0 + 9) * SJ + jb];
                float x6 = sHJT[(d0 + 8) * SJ + jb + 8];
                float x7 = sHJT[(d0 + 9) * SJ + jb + 8];
                uint32_t a0 = bf2_relu(hi0.x + x0, hi0.y + x1);  // row gr,  k d0
                uint32_t a1 = bf2_relu(hi0.x + x2, hi0.y + x3);  // row gr+8,k d0
                uint32_t a2 = bf2_relu(hi1.x + x4, hi1.y + x5);  // row gr,  k d0+8
                uint32_t a3 = bf2_relu(hi1.x + x6, hi1.y + x7);  // row gr+8,k d0+8
#pragma unroll
                for (int nt = 0; nt < 4; nt++) {
                    asm volatile(
                        "mma.sync.aligned.m16n8k16.row.col.f32.bf16.bf16.f32 "
                        "{%0,%1,%2,%3}, {%4,%5,%6,%7}, {%8,%9}, {%0,%1,%2,%3};"
                        : "+f"(cr[nt][0]), "+f"(cr[nt][1]),
                          "+f"(cr[nt][2]), "+f"(cr[nt][3])
                        : "r"(a0), "r"(a1), "r"(a2), "r"(a3),
                          "r"(Bf[kt][nt][0]), "r"(Bf[kt][nt][1]));
                }
            }

            // Epilogue: s_j = sum_k relu(D + b2[k]) * w3[k].
            float sj = 0.f, sj8 = 0.f;
#pragma unroll
            for (int nt = 0; nt < 4; nt++) {
                sj  += fmaxf(cr[nt][0] + b2v[nt * 2],     0.f) * w3v[nt * 2];
                sj  += fmaxf(cr[nt][1] + b2v[nt * 2 + 1], 0.f) * w3v[nt * 2 + 1];
                sj8 += fmaxf(cr[nt][2] + b2v[nt * 2],     0.f) * w3v[nt * 2];
                sj8 += fmaxf(cr[nt][3] + b2v[nt * 2 + 1], 0.f) * w3v[nt * 2 + 1];
            }
            sj  += __shfl_xor_sync(0xffffffffu, sj, 1);
            sj  += __shfl_xor_sync(0xffffffffu, sj, 2);
            sj8 += __shfl_xor_sync(0xffffffffu, sj8, 1);
            sj8 += __shfl_xor_sync(0xffffffffu, sj8, 2);

            if (c == 0) {
                int j = j0 + jb;
                float v0 = (j > i) ? 1.f / (1.f + __expf(-(sj + b3v))) : 0.f;
                out[(size_t)i * n + j] = v0;
                int j8 = j + 8;
                float v1 = (j8 > i) ? 1.f / (1.f + __expf(-(sj8 + b3v))) : 0.f;
                out[(size_t)i * n + j8] = v1;
            }
        }
    }
}

// ---------------- launch ----------------------------------------------------
extern "C" void kernel_launch(void* const* d_in, const int* in_sizes, int n_in,
                              void* d_out, int out_size)
{
    const int*   si = (const int*)d_in[0];
    const int*   ri = (const int*)d_in[1];
    const int*   oi = (const int*)d_in[2];
    const float* st = (const float*)d_in[3];
    const float* rt = (const float*)d_in[4];
    const float* ot = (const float*)d_in[5];
    const float* pw = (const float*)d_in[6];
    const float* pb = (const float*)d_in[7];
    const float* w1 = (const float*)d_in[8];
    const float* b1 = (const float*)d_in[9];
    const float* w2 = (const float*)d_in[10];
    const float* b2 = (const float*)d_in[11];
    const float* w3 = (const float*)d_in[12];
    const float* b3 = (const float*)d_in[13];
    float* out = (float*)d_out;
    const int n = in_sizes[0];

    p1_kernel<<<(41 * ED * 32 + 255) / 256, 256>>>(st, rt, ot, pw);
    p2_kernel<<<(2 * 41 * ED * 32 + 255) / 256, 256>>>(pb, w1, b1);

    int total = n * (ED / 4);
    gather_kernel<<<(total + 255) / 256, 256>>>(si, ri, oi, n);

    dim3 grid(n / TJ, n / TI);
    score_kernel<<<grid, 256>>>(w2, b2, w3, b3, out, n);
}

// round 9
// speedup vs baseline: 3.6208x; 1.1136x over previous
#include <cuda_runtime.h>
#include <cuda_bf16.h>
#include <math.h>
#include <cstdint>

#define ED    64      // embed dim
#define NKK   32      // w2 output dim
#define N_MAX 2048

// ---------------- device scratch (no allocations allowed) ----------------
// Rows 0..15 = subj, 16..24 = rel, 25..40 = obj. A = hi-side, B = hj-side.
__device__ float g_P[41 * ED];      // projected tables (stage 1)
__device__ float g_Atab[41 * ED];
__device__ float g_Btab[41 * ED];
// Packed bf16x2 per-row features: [n][d/2] (lo half = even d)
__device__ uint32_t g_HIh[N_MAX * (ED / 2)];
__device__ uint32_t g_HJh[N_MAX * (ED / 2)];

__device__ __forceinline__ float warp_sum(float v) {
#pragma unroll
    for (int s = 16; s; s >>= 1) v += __shfl_xor_sync(0xffffffffu, v, s);
    return v;
}

__device__ __forceinline__ uint32_t bf2(float lo, float hi) {
    uint32_t r;
    asm("cvt.rn.bf16x2.f32 %0, %1, %2;" : "=r"(r) : "f"(hi), "f"(lo));
    return r;
}
// a (+) b in bf16x2, then relu (max vs +0.0x2).
__device__ __forceinline__ uint32_t hadd2_relu(uint32_t a, uint32_t b) {
    uint32_t r;
    asm("add.rn.bf16x2 %0, %1, %2;" : "=r"(r) : "r"(a), "r"(b));
    asm("max.bf16x2 %0, %0, %1;" : "+r"(r) : "r"(0u));
    return r;
}

// ---------------- stage P1: projected tables, one warp per output ----------
__global__ void p1_kernel(const float* __restrict__ st,
                          const float* __restrict__ rt,
                          const float* __restrict__ ot,
                          const float* __restrict__ pw)   // [64][192]
{
    int warp = (blockIdx.x * blockDim.x + threadIdx.x) >> 5;
    int lane = threadIdx.x & 31;
    if (warp >= 41 * ED) return;
    int row = warp >> 6, k = warp & 63;
    const float* tab;
    int off;
    if (row < 16)      { tab = st + row * ED;        off = 0;   }
    else if (row < 25) { tab = rt + (row - 16) * ED; off = 64;  }
    else               { tab = ot + (row - 25) * ED; off = 128; }
    const float* wrow = pw + k * 192 + off;
    float v = tab[lane] * wrow[lane] + tab[lane + 32] * wrow[lane + 32];
    v = warp_sum(v);
    if (lane == 0) g_P[warp] = v;
}

// ---------------- stage P2: A/B tables, one warp per output ----------------
__global__ void p2_kernel(const float* __restrict__ pb,   // [64]
                          const float* __restrict__ w1,   // [64][128]
                          const float* __restrict__ b1)   // [64]
{
    int warp = (blockIdx.x * blockDim.x + threadIdx.x) >> 5;
    int lane = threadIdx.x & 31;
    if (warp >= 2 * 41 * ED) return;
    int side = warp / (41 * ED);
    int rem  = warp % (41 * ED);
    int row = rem >> 6, d = rem & 63;
    const float* w1row = w1 + d * 128 + side * 64;
    const float* Prow  = g_P + row * ED;
    float v = Prow[lane] * w1row[lane] + Prow[lane + 32] * w1row[lane + 32];
    if (row >= 25)
        v += pb[lane] * w1row[lane] + pb[lane + 32] * w1row[lane + 32];
    v = warp_sum(v);
    if (lane == 0) {
        if (row >= 25 && side == 1) v += b1[d];
        if (side) g_Btab[rem] = v;
        else      g_Atab[rem] = v;
    }
}

// ---------------- gather -> HI/HJ packed bf16x2, [n][d/2] ------------------
__global__ void gather_kernel(const int* __restrict__ si,
                              const int* __restrict__ ri,
                              const int* __restrict__ oi, int n)
{
    int g = blockIdx.x * blockDim.x + threadIdx.x;
    if (g >= n * (ED / 4)) return;
    int nn = g >> 4;
    int c  = (g & 15) * 4;
    int s = si[nn], r = ri[nn], o = oi[nn];

    float4 a0 = *(const float4*)&g_Atab[s * ED + c];
    float4 a1 = *(const float4*)&g_Atab[(16 + r) * ED + c];
    float4 a2 = *(const float4*)&g_Atab[(25 + o) * ED + c];
    uint2 hi;
    hi.x = bf2(a0.x + a1.x + a2.x, a0.y + a1.y + a2.y);
    hi.y = bf2(a0.z + a1.z + a2.z, a0.w + a1.w + a2.w);
    *(uint2*)&g_HIh[nn * 32 + c / 2] = hi;

    float4 b0 = *(const float4*)&g_Btab[s * ED + c];
    float4 b1v = *(const float4*)&g_Btab[(16 + r) * ED + c];
    float4 b2v = *(const float4*)&g_Btab[(25 + o) * ED + c];
    uint2 hj;
    hj.x = bf2(b0.x + b1v.x + b2v.x, b0.y + b1v.y + b2v.y);
    hj.y = bf2(b0.z + b1v.z + b2v.z, b0.w + b1v.w + b2v.w);
    *(uint2*)&g_HJh[nn * 32 + c / 2] = hj;
}

// ---------------- score kernel: mma.sync bf16, packed-bf16 A build ---------
// CTA tile = 64 i x 32 j. Warp w owns i-rows w*8..w*8+7. One m16 MMA tile =
// one i x 16 j's (j -> MMA M-rows, k_out -> N, d -> K).
//   D[j][k] = sum_d relu(hi[i][d] (+) hj[j][d]) * w2[k][d]   (bf16 adds)
#define TI 64
#define TJ 32
#define SJ2 40  // hjT2 row stride (words): mainloop bank = 8c+gr, conflict-free

__global__ void __launch_bounds__(256)
score_kernel(const float* __restrict__ w2,   // [32][64]
             const float* __restrict__ b2,   // [32]
             const float* __restrict__ w3,   // [1][32]
             const float* __restrict__ b3,   // [1]
             float* __restrict__ out, int n)
{
    const int t = threadIdx.x, w = t >> 5, lane = t & 31;
    const int gr = lane >> 2, c = lane & 3;
    const int i0 = blockIdx.y * TI, j0 = blockIdx.x * TJ;

    // Tile entirely at/below diagonal -> pure zeros.
    if (j0 + TJ - 1 <= i0) {
        const float4 z = make_float4(0.f, 0.f, 0.f, 0.f);
#pragma unroll
        for (int q = 0; q < 2; q++) {
            int idx = q * 256 + t;
            int r = idx >> 3, f4 = (idx & 7) * 4;
            *(float4*)&out[(size_t)(i0 + r) * n + j0 + f4] = z;
        }
        return;
    }

    __shared__ __align__(16) uint32_t sHIh[TI * 32];      // [i][d2], 8KB
    __shared__ uint32_t sHJT2[32 * SJ2];                  // [d2][j], 5KB

    // Stage hi rows (coalesced uint4: 8 threads per 128B row).
#pragma unroll
    for (int q = 0; q < 2; q++) {
        int idx = q * 256 + t;
        int r = idx >> 3, w4 = (idx & 7) * 4;
        *(uint4*)&sHIh[r * 32 + w4] = *(const uint4*)&g_HIh[(i0 + r) * 32 + w4];
    }
    // Stage hj transposed: sHJT2[d2][j] = packed hj(j0+j, 2*d2, 2*d2+1).
    // One uint4 (8 bf16 = 4 d2) per thread; j = lane -> conflict-free writes.
    {
        int j = t & 31, dg = t >> 5;           // dg*4 .. dg*4+3 d2-words
        uint4 v = *(const uint4*)&g_HJh[(j0 + j) * 32 + dg * 4];
        sHJT2[(dg * 4 + 0) * SJ2 + j] = v.x;
        sHJT2[(dg * 4 + 1) * SJ2 + j] = v.y;
        sHJT2[(dg * 4 + 2) * SJ2 + j] = v.z;
        sHJT2[(dg * 4 + 3) * SJ2 + j] = v.w;
    }

    // Preload B fragments: Bf[kt][nt][r]; n = nt*8+gr, k = kt*16+2c (+8).
    uint32_t Bf[4][4][2];
#pragma unroll
    for (int kt = 0; kt < 4; kt++)
#pragma unroll
        for (int nt = 0; nt < 4; nt++) {
            const float* wrow = w2 + (nt * 8 + gr) * ED + kt * 16 + 2 * c;
            float2 wa = *(const float2*)&wrow[0];
            float2 wb = *(const float2*)&wrow[8];
            Bf[kt][nt][0] = bf2(wa.x, wa.y);
            Bf[kt][nt][1] = bf2(wb.x, wb.y);
        }
    // Per-thread epilogue constants for cols nt*8 + 2c, +1.
    float b2v[8], w3v[8];
#pragma unroll
    for (int nt = 0; nt < 4; nt++) {
        float2 bb = *(const float2*)&b2[nt * 8 + 2 * c];
        float2 ww = *(const float2*)&w3[nt * 8 + 2 * c];
        b2v[nt * 2] = bb.x; b2v[nt * 2 + 1] = bb.y;
        w3v[nt * 2] = ww.x; w3v[nt * 2 + 1] = ww.y;
    }
    const float b3v = b3[0];
    __syncthreads();

#pragma unroll 1
    for (int il = 0; il < 8; il++) {
        const int i = i0 + w * 8 + il;
        const uint32_t* hiRow = sHIh + (w * 8 + il) * 32;
#pragma unroll
        for (int jt = 0; jt < 2; jt++) {
            float cr[4][4];
#pragma unroll
            for (int nt = 0; nt < 4; nt++)
#pragma unroll
                for (int r = 0; r < 4; r++) cr[nt][r] = 0.f;

            const int jb = jt * 16 + gr;
#pragma unroll
            for (int kt = 0; kt < 4; kt++) {
                const int d2a = kt * 8 + c;            // packs d0, d0+1
                uint32_t hi0 = hiRow[d2a];             // bank broadcast
                uint32_t hi1 = hiRow[d2a + 4];         // d0+8, d0+9
                uint32_t hj0 = sHJT2[d2a * SJ2 + jb];
                uint32_t hj1 = sHJT2[d2a * SJ2 + jb + 8];
                uint32_t hj2 = sHJT2[(d2a + 4) * SJ2 + jb];
                uint32_t hj3 = sHJT2[(d2a + 4) * SJ2 + jb + 8];
                uint32_t a0 = hadd2_relu(hi0, hj0);    // row gr,   k d0
                uint32_t a1 = hadd2_relu(hi0, hj1);    // row gr+8, k d0
                uint32_t a2 = hadd2_relu(hi1, hj2);    // row gr,   k d0+8
                uint32_t a3 = hadd2_relu(hi1, hj3);    // row gr+8, k d0+8
#pragma unroll
                for (int nt = 0; nt < 4; nt++) {
                    asm volatile(
                        "mma.sync.aligned.m16n8k16.row.col.f32.bf16.bf16.f32 "
                        "{%0,%1,%2,%3}, {%4,%5,%6,%7}, {%8,%9}, {%0,%1,%2,%3};"
                        : "+f"(cr[nt][0]), "+f"(cr[nt][1]),
                          "+f"(cr[nt][2]), "+f"(cr[nt][3])
                        : "r"(a0), "r"(a1), "r"(a2), "r"(a3),
                          "r"(Bf[kt][nt][0]), "r"(Bf[kt][nt][1]));
                }
            }

            // Epilogue: s_j = sum_k relu(D + b2[k]) * w3[k].
            float sj = 0.f, sj8 = 0.f;
#pragma unroll
            for (int nt = 0; nt < 4; nt++) {
                sj  += fmaxf(cr[nt][0] + b2v[nt * 2],     0.f) * w3v[nt * 2];
                sj  += fmaxf(cr[nt][1] + b2v[nt * 2 + 1], 0.f) * w3v[nt * 2 + 1];
                sj8 += fmaxf(cr[nt][2] + b2v[nt * 2],     0.f) * w3v[nt * 2];
                sj8 += fmaxf(cr[nt][3] + b2v[nt * 2 + 1], 0.f) * w3v[nt * 2 + 1];
            }
            sj  += __shfl_xor_sync(0xffffffffu, sj, 1);
            sj  += __shfl_xor_sync(0xffffffffu, sj, 2);
            sj8 += __shfl_xor_sync(0xffffffffu, sj8, 1);
            sj8 += __shfl_xor_sync(0xffffffffu, sj8, 2);

            if (c == 0) {
                int j = j0 + jb;
                float v0 = (j > i) ? 1.f / (1.f + __expf(-(sj + b3v))) : 0.f;
                out[(size_t)i * n + j] = v0;
                int j8 = j + 8;
                float v1 = (j8 > i) ? 1.f / (1.f + __expf(-(sj8 + b3v))) : 0.f;
                out[(size_t)i * n + j8] = v1;
            }
        }
    }
}

// ---------------- launch ----------------------------------------------------
extern "C" void kernel_launch(void* const* d_in, const int* in_sizes, int n_in,
                              void* d_out, int out_size)
{
    const int*   si = (const int*)d_in[0];
    const int*   ri = (const int*)d_in[1];
    const int*   oi = (const int*)d_in[2];
    const float* st = (const float*)d_in[3];
    const float* rt = (const float*)d_in[4];
    const float* ot = (const float*)d_in[5];
    const float* pw = (const float*)d_in[6];
    const float* pb = (const float*)d_in[7];
    const float* w1 = (const float*)d_in[8];
    const float* b1 = (const float*)d_in[9];
    const float* w2 = (const float*)d_in[10];
    const float* b2 = (const float*)d_in[11];
    const float* w3 = (const float*)d_in[12];
    const float* b3 = (const float*)d_in[13];
    float* out = (float*)d_out;
    const int n = in_sizes[0];

    p1_kernel<<<(41 * ED * 32 + 255) / 256, 256>>>(st, rt, ot, pw);
    p2_kernel<<<(2 * 41 * ED * 32 + 255) / 256, 256>>>(pb, w1, b1);

    int total = n * (ED / 4);
    gather_kernel<<<(total + 255) / 256, 256>>>(si, ri, oi, n);

    dim3 grid(n / TJ, n / TI);
    score_kernel<<<grid, 256>>>(w2, b2, w3, b3, out, n);
}

// round 10
// speedup vs baseline: 4.2597x; 1.1764x over previous
#include <cuda_runtime.h>
#include <cuda_bf16.h>
#include <math.h>
#include <cstdint>

#define ED    64      // embed dim
#define NKK   32      // w2 output dim
#define N_MAX 2048

// ---------------- device scratch (no allocations allowed) ----------------
__device__ float g_P[41 * ED];      // projected tables (stage 1)
__device__ float g_Atab[41 * ED];
__device__ float g_Btab[41 * ED];
// Packed bf16x2 per-row features: [n][d/2] (lo half = even d)
__device__ uint32_t g_HIh[N_MAX * (ED / 2)];
__device__ uint32_t g_HJh[N_MAX * (ED / 2)];

__device__ __forceinline__ float warp_sum(float v) {
#pragma unroll
    for (int s = 16; s; s >>= 1) v += __shfl_xor_sync(0xffffffffu, v, s);
    return v;
}

__device__ __forceinline__ uint32_t bf2(float lo, float hi) {
    uint32_t r;
    asm("cvt.rn.bf16x2.f32 %0, %1, %2;" : "=r"(r) : "f"(hi), "f"(lo));
    return r;
}
// a (+) b in bf16x2, then relu (max vs +0.0x2).
__device__ __forceinline__ uint32_t hadd2_relu(uint32_t a, uint32_t b) {
    uint32_t r;
    asm("add.rn.bf16x2 %0, %1, %2;" : "=r"(r) : "r"(a), "r"(b));
    asm("max.bf16x2 %0, %0, %1;" : "+r"(r) : "r"(0u));
    return r;
}

// ---------------- stage P1: projected tables, one warp per output ----------
__global__ void p1_kernel(const float* __restrict__ st,
                          const float* __restrict__ rt,
                          const float* __restrict__ ot,
                          const float* __restrict__ pw)   // [64][192]
{
    int warp = (blockIdx.x * blockDim.x + threadIdx.x) >> 5;
    int lane = threadIdx.x & 31;
    if (warp >= 41 * ED) return;
    int row = warp >> 6, k = warp & 63;
    const float* tab;
    int off;
    if (row < 16)      { tab = st + row * ED;        off = 0;   }
    else if (row < 25) { tab = rt + (row - 16) * ED; off = 64;  }
    else               { tab = ot + (row - 25) * ED; off = 128; }
    const float* wrow = pw + k * 192 + off;
    float v = tab[lane] * wrow[lane] + tab[lane + 32] * wrow[lane + 32];
    v = warp_sum(v);
    if (lane == 0) g_P[warp] = v;
}

// ---------------- stage P2: A/B tables, one warp per output ----------------
__global__ void p2_kernel(const float* __restrict__ pb,   // [64]
                          const float* __restrict__ w1,   // [64][128]
                          const float* __restrict__ b1)   // [64]
{
    int warp = (blockIdx.x * blockDim.x + threadIdx.x) >> 5;
    int lane = threadIdx.x & 31;
    if (warp >= 2 * 41 * ED) return;
    int side = warp / (41 * ED);
    int rem  = warp % (41 * ED);
    int row = rem >> 6, d = rem & 63;
    const float* w1row = w1 + d * 128 + side * 64;
    const float* Prow  = g_P + row * ED;
    float v = Prow[lane] * w1row[lane] + Prow[lane + 32] * w1row[lane + 32];
    if (row >= 25)
        v += pb[lane] * w1row[lane] + pb[lane + 32] * w1row[lane + 32];
    v = warp_sum(v);
    if (lane == 0) {
        if (row >= 25 && side == 1) v += b1[d];
        if (side) g_Btab[rem] = v;
        else      g_Atab[rem] = v;
    }
}

// ---------------- gather -> HI/HJ packed bf16x2, [n][d/2] ------------------
__global__ void gather_kernel(const int* __restrict__ si,
                              const int* __restrict__ ri,
                              const int* __restrict__ oi, int n)
{
    int g = blockIdx.x * blockDim.x + threadIdx.x;
    if (g >= n * (ED / 4)) return;
    int nn = g >> 4;
    int c  = (g & 15) * 4;
    int s = si[nn], r = ri[nn], o = oi[nn];

    float4 a0 = *(const float4*)&g_Atab[s * ED + c];
    float4 a1 = *(const float4*)&g_Atab[(16 + r) * ED + c];
    float4 a2 = *(const float4*)&g_Atab[(25 + o) * ED + c];
    uint2 hi;
    hi.x = bf2(a0.x + a1.x + a2.x, a0.y + a1.y + a2.y);
    hi.y = bf2(a0.z + a1.z + a2.z, a0.w + a1.w + a2.w);
    *(uint2*)&g_HIh[nn * 32 + c / 2] = hi;

    float4 b0 = *(const float4*)&g_Btab[s * ED + c];
    float4 b1v = *(const float4*)&g_Btab[(16 + r) * ED + c];
    float4 b2v = *(const float4*)&g_Btab[(25 + o) * ED + c];
    uint2 hj;
    hj.x = bf2(b0.x + b1v.x + b2v.x, b0.y + b1v.y + b2v.y);
    hj.y = bf2(b0.z + b1v.z + b2v.z, b0.w + b1v.w + b2v.w);
    *(uint2*)&g_HJh[nn * 32 + c / 2] = hj;
}

// ---------------- score kernel: mma.sync bf16, occupancy-tuned -------------
// CTA tile = 64 i x 32 j. Warp w owns i-rows w*8..w*8+7. One m16 MMA tile =
// one i x 16 j's (j -> MMA M-rows, k_out -> N, d -> K).
// B fragments live in SMEM (LDS.64 at 2*lane: conflict-free); hj fragments
// cached in registers per jt; 3 CTAs/SM.
#define TI 64
#define TJ 32
#define SJ2 40  // hjT2 row stride (words): bank = 8c+gr, conflict-free

__global__ void __launch_bounds__(256, 3)
score_kernel(const float* __restrict__ w2,   // [32][64]
             const float* __restrict__ b2,   // [32]
             const float* __restrict__ w3,   // [1][32]
             const float* __restrict__ b3,   // [1]
             float* __restrict__ out, int n)
{
    const int t = threadIdx.x, w = t >> 5, lane = t & 31;
    const int gr = lane >> 2, c = lane & 3;
    const int i0 = blockIdx.y * TI, j0 = blockIdx.x * TJ;

    // Tile entirely at/below diagonal -> pure zeros.
    if (j0 + TJ - 1 <= i0) {
        const float4 z = make_float4(0.f, 0.f, 0.f, 0.f);
#pragma unroll
        for (int q = 0; q < 2; q++) {
            int idx = q * 256 + t;
            int r = idx >> 3, f4 = (idx & 7) * 4;
            *(float4*)&out[(size_t)(i0 + r) * n + j0 + f4] = z;
        }
        return;
    }

    __shared__ __align__(16) uint32_t sHIh[TI * 32];      // [i][d2], 8KB
    __shared__ uint32_t sHJT2[32 * SJ2];                  // [d2][j], 5KB
    // B fragments: entry e=(kt*4+nt)*32 + lane, two words (r=0,1) each.
    __shared__ __align__(8) uint32_t sW2f[4 * 4 * 32 * 2];  // 4KB

    // Stage hi rows (coalesced uint4: 8 threads per 128B row).
#pragma unroll
    for (int q = 0; q < 2; q++) {
        int idx = q * 256 + t;
        int r = idx >> 3, w4 = (idx & 7) * 4;
        *(uint4*)&sHIh[r * 32 + w4] = *(const uint4*)&g_HIh[(i0 + r) * 32 + w4];
    }
    // Stage hj transposed: sHJT2[d2][j] = packed hj(j0+j, 2*d2, 2*d2+1).
    {
        int j = t & 31, dg = t >> 5;           // dg*4 .. dg*4+3 d2-words
        uint4 v = *(const uint4*)&g_HJh[(j0 + j) * 32 + dg * 4];
        sHJT2[(dg * 4 + 0) * SJ2 + j] = v.x;
        sHJT2[(dg * 4 + 1) * SJ2 + j] = v.y;
        sHJT2[(dg * 4 + 2) * SJ2 + j] = v.z;
        sHJT2[(dg * 4 + 3) * SJ2 + j] = v.w;
    }
    // Stage B fragments into SMEM: e = (kt,nt,gr,c); lane reads e*2 (LDS.64).
#pragma unroll
    for (int q = 0; q < 2; q++) {
        int e  = q * 256 + t;
        int kt = e >> 7, nt = (e >> 5) & 3, ln = e & 31;
        int row = nt * 8 + (ln >> 2);           // w2 row (k_out)
        int col = kt * 16 + 2 * (ln & 3);       // w2 col (d)
        const float* wr = w2 + row * ED + col;
        sW2f[e * 2]     = bf2(wr[0], wr[1]);
        sW2f[e * 2 + 1] = bf2(wr[8], wr[9]);
    }
    // Per-thread epilogue constants for cols nt*8 + 2c, +1.
    float b2v[8], w3v[8];
#pragma unroll
    for (int nt = 0; nt < 4; nt++) {
        float2 bb = *(const float2*)&b2[nt * 8 + 2 * c];
        float2 ww = *(const float2*)&w3[nt * 8 + 2 * c];
        b2v[nt * 2] = bb.x; b2v[nt * 2 + 1] = bb.y;
        w3v[nt * 2] = ww.x; w3v[nt * 2 + 1] = ww.y;
    }
    const float b3v = b3[0];
    __syncthreads();

#pragma unroll
    for (int jt = 0; jt < 2; jt++) {
        const int jb = jt * 16 + gr;
        // hj fragments for this jt, all kt: cached across the il loop.
        uint32_t hjr[4][4];
#pragma unroll
        for (int kt = 0; kt < 4; kt++) {
            const int d2a = kt * 8 + c;
            hjr[kt][0] = sHJT2[d2a * SJ2 + jb];
            hjr[kt][1] = sHJT2[d2a * SJ2 + jb + 8];
            hjr[kt][2] = sHJT2[(d2a + 4) * SJ2 + jb];
            hjr[kt][3] = sHJT2[(d2a + 4) * SJ2 + jb + 8];
        }
#pragma unroll 1
        for (int il = 0; il < 8; il++) {
            const int i = i0 + w * 8 + il;
            const uint32_t* hiRow = sHIh + (w * 8 + il) * 32;
            uint32_t hir[8];
#pragma unroll
            for (int kt = 0; kt < 4; kt++) {
                hir[kt * 2]     = hiRow[kt * 8 + c];
                hir[kt * 2 + 1] = hiRow[kt * 8 + c + 4];
            }
            float cr[4][4];
#pragma unroll
            for (int nt = 0; nt < 4; nt++)
#pragma unroll
                for (int r = 0; r < 4; r++) cr[nt][r] = 0.f;

#pragma unroll
            for (int kt = 0; kt < 4; kt++) {
                uint32_t a0 = hadd2_relu(hir[kt * 2],     hjr[kt][0]);
                uint32_t a1 = hadd2_relu(hir[kt * 2],     hjr[kt][1]);
                uint32_t a2 = hadd2_relu(hir[kt * 2 + 1], hjr[kt][2]);
                uint32_t a3 = hadd2_relu(hir[kt * 2 + 1], hjr[kt][3]);
#pragma unroll
                for (int nt = 0; nt < 4; nt++) {
                    uint2 bw = *(const uint2*)&sW2f[((kt * 4 + nt) * 32 + lane) * 2];
                    asm volatile(
                        "mma.sync.aligned.m16n8k16.row.col.f32.bf16.bf16.f32 "
                        "{%0,%1,%2,%3}, {%4,%5,%6,%7}, {%8,%9}, {%0,%1,%2,%3};"
                        : "+f"(cr[nt][0]), "+f"(cr[nt][1]),
                          "+f"(cr[nt][2]), "+f"(cr[nt][3])
                        : "r"(a0), "r"(a1), "r"(a2), "r"(a3),
                          "r"(bw.x), "r"(bw.y));
                }
            }

            // Epilogue: s_j = sum_k relu(D + b2[k]) * w3[k].
            float sj = 0.f, sj8 = 0.f;
#pragma unroll
            for (int nt = 0; nt < 4; nt++) {
                sj  += fmaxf(cr[nt][0] + b2v[nt * 2],     0.f) * w3v[nt * 2];
                sj  += fmaxf(cr[nt][1] + b2v[nt * 2 + 1], 0.f) * w3v[nt * 2 + 1];
                sj8 += fmaxf(cr[nt][2] + b2v[nt * 2],     0.f) * w3v[nt * 2];
                sj8 += fmaxf(cr[nt][3] + b2v[nt * 2 + 1], 0.f) * w3v[nt * 2 + 1];
            }
            sj  += __shfl_xor_sync(0xffffffffu, sj, 1);
            sj  += __shfl_xor_sync(0xffffffffu, sj, 2);
            sj8 += __shfl_xor_sync(0xffffffffu, sj8, 1);
            sj8 += __shfl_xor_sync(0xffffffffu, sj8, 2);

            if (c == 0) {
                int j = j0 + jb;
                float v0 = (j > i) ? 1.f / (1.f + __expf(-(sj + b3v))) : 0.f;
                out[(size_t)i * n + j] = v0;
                int j8 = j + 8;
                float v1 = (j8 > i) ? 1.f / (1.f + __expf(-(sj8 + b3v))) : 0.f;
                out[(size_t)i * n + j8] = v1;
            }
        }
    }
}

// ---------------- launch ----------------------------------------------------
extern "C" void kernel_launch(void* const* d_in, const int* in_sizes, int n_in,
                              void* d_out, int out_size)
{
    const int*   si = (const int*)d_in[0];
    const int*   ri = (const int*)d_in[1];
    const int*   oi = (const int*)d_in[2];
    const float* st = (const float*)d_in[3];
    const float* rt = (const float*)d_in[4];
    const float* ot = (const float*)d_in[5];
    const float* pw = (const float*)d_in[6];
    const float* pb = (const float*)d_in[7];
    const float* w1 = (const float*)d_in[8];
    const float* b1 = (const float*)d_in[9];
    const float* w2 = (const float*)d_in[10];
    const float* b2 = (const float*)d_in[11];
    const float* w3 = (const float*)d_in[12];
    const float* b3 = (const float*)d_in[13];
    float* out = (float*)d_out;
    const int n = in_sizes[0];

    p1_kernel<<<(41 * ED * 32 + 255) / 256, 256>>>(st, rt, ot, pw);
    p2_kernel<<<(2 * 41 * ED * 32 + 255) / 256, 256>>>(pb, w1, b1);

    int total = n * (ED / 4);
    gather_kernel<<<(total + 255) / 256, 256>>>(si, ri, oi, n);

    dim3 grid(n / TJ, n / TI);
    score_kernel<<<grid, 256>>>(w2, b2, w3, b3, out, n);
}

// round 11
// speedup vs baseline: 4.4997x; 1.0563x over previous
#include <cuda_runtime.h>
#include <cuda_bf16.h>
#include <math.h>
#include <cstdint>

#define ED    64      // embed dim
#define NKK   32      // w2 output dim
#define N_MAX 2048

// ---------------- device scratch (no allocations allowed) ----------------
__device__ float g_P[41 * ED];      // projected tables (stage 1)
__device__ float g_Atab[41 * ED];
__device__ float g_Btab[41 * ED];
// Packed bf16x2 per-row features: [n][d/2] (lo half = even d)
__device__ uint32_t g_HIh[N_MAX * (ED / 2)];
__device__ uint32_t g_HJh[N_MAX * (ED / 2)];

__device__ __forceinline__ float warp_sum(float v) {
#pragma unroll
    for (int s = 16; s; s >>= 1) v += __shfl_xor_sync(0xffffffffu, v, s);
    return v;
}

__device__ __forceinline__ uint32_t bf2(float lo, float hi) {
    uint32_t r;
    asm("cvt.rn.bf16x2.f32 %0, %1, %2;" : "=r"(r) : "f"(hi), "f"(lo));
    return r;
}
// a (+) b in bf16x2, then relu (max vs +0.0x2).
__device__ __forceinline__ uint32_t hadd2_relu(uint32_t a, uint32_t b) {
    uint32_t r;
    asm("add.rn.bf16x2 %0, %1, %2;" : "=r"(r) : "r"(a), "r"(b));
    asm("max.bf16x2 %0, %0, %1;" : "+r"(r) : "r"(0u));
    return r;
}
// pack two f32 -> bf16x2 then relu.
__device__ __forceinline__ uint32_t pk_relu(float lo, float hi) {
    uint32_t r;
    asm("cvt.rn.bf16x2.f32 %0, %1, %2;" : "=r"(r) : "f"(hi), "f"(lo));
    asm("max.bf16x2 %0, %0, %1;" : "+r"(r) : "r"(0u));
    return r;
}

// ---------------- stage P1: projected tables, one warp per output ----------
__global__ void p1_kernel(const float* __restrict__ st,
                          const float* __restrict__ rt,
                          const float* __restrict__ ot,
                          const float* __restrict__ pw)   // [64][192]
{
    int warp = (blockIdx.x * blockDim.x + threadIdx.x) >> 5;
    int lane = threadIdx.x & 31;
    if (warp >= 41 * ED) return;
    int row = warp >> 6, k = warp & 63;
    const float* tab;
    int off;
    if (row < 16)      { tab = st + row * ED;        off = 0;   }
    else if (row < 25) { tab = rt + (row - 16) * ED; off = 64;  }
    else               { tab = ot + (row - 25) * ED; off = 128; }
    const float* wrow = pw + k * 192 + off;
    float v = tab[lane] * wrow[lane] + tab[lane + 32] * wrow[lane + 32];
    v = warp_sum(v);
    if (lane == 0) g_P[warp] = v;
}

// ---------------- stage P2: A/B tables, one warp per output ----------------
__global__ void p2_kernel(const float* __restrict__ pb,   // [64]
                          const float* __restrict__ w1,   // [64][128]
                          const float* __restrict__ b1)   // [64]
{
    int warp = (blockIdx.x * blockDim.x + threadIdx.x) >> 5;
    int lane = threadIdx.x & 31;
    if (warp >= 2 * 41 * ED) return;
    int side = warp / (41 * ED);
    int rem  = warp % (41 * ED);
    int row = rem >> 6, d = rem & 63;
    const float* w1row = w1 + d * 128 + side * 64;
    const float* Prow  = g_P + row * ED;
    float v = Prow[lane] * w1row[lane] + Prow[lane + 32] * w1row[lane + 32];
    if (row >= 25)
        v += pb[lane] * w1row[lane] + pb[lane + 32] * w1row[lane + 32];
    v = warp_sum(v);
    if (lane == 0) {
        if (row >= 25 && side == 1) v += b1[d];
        if (side) g_Btab[rem] = v;
        else      g_Atab[rem] = v;
    }
}

// ---------------- gather -> HI/HJ packed bf16x2, [n][d/2] ------------------
__global__ void gather_kernel(const int* __restrict__ si,
                              const int* __restrict__ ri,
                              const int* __restrict__ oi, int n)
{
    int g = blockIdx.x * blockDim.x + threadIdx.x;
    if (g >= n * (ED / 4)) return;
    int nn = g >> 4;
    int c  = (g & 15) * 4;
    int s = si[nn], r = ri[nn], o = oi[nn];

    float4 a0 = *(const float4*)&g_Atab[s * ED + c];
    float4 a1 = *(const float4*)&g_Atab[(16 + r) * ED + c];
    float4 a2 = *(const float4*)&g_Atab[(25 + o) * ED + c];
    uint2 hi;
    hi.x = bf2(a0.x + a1.x + a2.x, a0.y + a1.y + a2.y);
    hi.y = bf2(a0.z + a1.z + a2.z, a0.w + a1.w + a2.w);
    *(uint2*)&g_HIh[nn * 32 + c / 2] = hi;

    float4 b0 = *(const float4*)&g_Btab[s * ED + c];
    float4 b1v = *(const float4*)&g_Btab[(16 + r) * ED + c];
    float4 b2v = *(const float4*)&g_Btab[(25 + o) * ED + c];
    uint2 hj;
    hj.x = bf2(b0.x + b1v.x + b2v.x, b0.y + b1v.y + b2v.y);
    hj.y = bf2(b0.z + b1v.z + b2v.z, b0.w + b1v.w + b2v.w);
    *(uint2*)&g_HJh[nn * 32 + c / 2] = hj;
}

// ---------------- score kernel: chained mma.sync bf16 ----------------------
// CTA tile = 64 i x 32 j. Warp w owns i-rows w*8..w*8+7. MMA1: 16 j-pairs x
// 32 k_out over d (b2 folded into accumulator init). MMA2 (chained): D1
// fragment relu'd/packed in-place becomes the A fragment of a second MMA
// against a w3-duplicated B: s lands in lanes c==0 with no shuffle; b3 is
// the MMA2 accumulator init.
#define TI 64
#define TJ 32
#define SJ2 40  // hjT2 row stride (words): bank = 8c+gr, conflict-free

__global__ void __launch_bounds__(256, 3)
score_kernel(const float* __restrict__ w2,   // [32][64]
             const float* __restrict__ b2,   // [32]
             const float* __restrict__ w3,   // [1][32]
             const float* __restrict__ b3,   // [1]
             float* __restrict__ out, int n)
{
    const int t = threadIdx.x, w = t >> 5, lane = t & 31;
    const int gr = lane >> 2, c = lane & 3;
    const int i0 = blockIdx.y * TI, j0 = blockIdx.x * TJ;

    // Tile entirely at/below diagonal -> pure zeros.
    if (j0 + TJ - 1 <= i0) {
        const float4 z = make_float4(0.f, 0.f, 0.f, 0.f);
#pragma unroll
        for (int q = 0; q < 2; q++) {
            int idx = q * 256 + t;
            int r = idx >> 3, f4 = (idx & 7) * 4;
            *(float4*)&out[(size_t)(i0 + r) * n + j0 + f4] = z;
        }
        return;
    }

    __shared__ __align__(16) uint32_t sHIh[TI * 32];      // [i][d2], 8KB
    __shared__ uint32_t sHJT2[32 * SJ2];                  // [d2][j], 5KB
    // B fragments: entry e=(kt*4+nt)*32 + lane, two words (r=0,1) each.
    __shared__ __align__(8) uint32_t sW2f[4 * 4 * 32 * 2];  // 4KB

    // Stage hi rows (coalesced uint4: 8 threads per 128B row).
#pragma unroll
    for (int q = 0; q < 2; q++) {
        int idx = q * 256 + t;
        int r = idx >> 3, w4 = (idx & 7) * 4;
        *(uint4*)&sHIh[r * 32 + w4] = *(const uint4*)&g_HIh[(i0 + r) * 32 + w4];
    }
    // Stage hj transposed: sHJT2[d2][j] = packed hj(j0+j, 2*d2, 2*d2+1).
    {
        int j = t & 31, dg = t >> 5;           // dg*4 .. dg*4+3 d2-words
        uint4 v = *(const uint4*)&g_HJh[(j0 + j) * 32 + dg * 4];
        sHJT2[(dg * 4 + 0) * SJ2 + j] = v.x;
        sHJT2[(dg * 4 + 1) * SJ2 + j] = v.y;
        sHJT2[(dg * 4 + 2) * SJ2 + j] = v.z;
        sHJT2[(dg * 4 + 3) * SJ2 + j] = v.w;
    }
    // Stage B fragments into SMEM: e = (kt,nt,gr,c); lane reads e*2 (LDS.64).
#pragma unroll
    for (int q = 0; q < 2; q++) {
        int e  = q * 256 + t;
        int kt = e >> 7, nt = (e >> 5) & 3, ln = e & 31;
        int row = nt * 8 + (ln >> 2);           // w2 row (k_out)
        int col = kt * 16 + 2 * (ln & 3);       // w2 col (d)
        const float* wr = w2 + row * ED + col;
        sW2f[e * 2]     = bf2(wr[0], wr[1]);
        sW2f[e * 2 + 1] = bf2(wr[8], wr[9]);
    }
    // MMA1 accumulator init values (= b2 for cols nt*8 + 2c, +1).
    float b2v[8];
#pragma unroll
    for (int nt = 0; nt < 4; nt++) {
        float2 bb = *(const float2*)&b2[nt * 8 + 2 * c];
        b2v[nt * 2] = bb.x; b2v[nt * 2 + 1] = bb.y;
    }
    // MMA2 B fragments: w3 duplicated across all N-columns (no gr term).
    uint32_t w3f[2][2];
#pragma unroll
    for (int kt2 = 0; kt2 < 2; kt2++) {
        const float* wr = w3 + kt2 * 16 + 2 * c;
        w3f[kt2][0] = bf2(wr[0], wr[1]);
        w3f[kt2][1] = bf2(wr[8], wr[9]);
    }
    const float b3v = b3[0];
    __syncthreads();

#pragma unroll
    for (int jt = 0; jt < 2; jt++) {
        const int jb = jt * 16 + gr;
        // hj fragments for this jt, all kt: cached across the il loop.
        uint32_t hjr[4][4];
#pragma unroll
        for (int kt = 0; kt < 4; kt++) {
            const int d2a = kt * 8 + c;
            hjr[kt][0] = sHJT2[d2a * SJ2 + jb];
            hjr[kt][1] = sHJT2[d2a * SJ2 + jb + 8];
            hjr[kt][2] = sHJT2[(d2a + 4) * SJ2 + jb];
            hjr[kt][3] = sHJT2[(d2a + 4) * SJ2 + jb + 8];
        }
#pragma unroll 1
        for (int il = 0; il < 8; il++) {
            const int i = i0 + w * 8 + il;
            const uint32_t* hiRow = sHIh + (w * 8 + il) * 32;
            uint32_t hir[8];
#pragma unroll
            for (int kt = 0; kt < 4; kt++) {
                hir[kt * 2]     = hiRow[kt * 8 + c];
                hir[kt * 2 + 1] = hiRow[kt * 8 + c + 4];
            }
            // MMA1 accumulators init = b2 (bias folded in).
            float cr[4][4];
#pragma unroll
            for (int nt = 0; nt < 4; nt++) {
                cr[nt][0] = b2v[nt * 2]; cr[nt][1] = b2v[nt * 2 + 1];
                cr[nt][2] = b2v[nt * 2]; cr[nt][3] = b2v[nt * 2 + 1];
            }

#pragma unroll
            for (int kt = 0; kt < 4; kt++) {
                uint32_t a0 = hadd2_relu(hir[kt * 2],     hjr[kt][0]);
                uint32_t a1 = hadd2_relu(hir[kt * 2],     hjr[kt][1]);
                uint32_t a2 = hadd2_relu(hir[kt * 2 + 1], hjr[kt][2]);
                uint32_t a3 = hadd2_relu(hir[kt * 2 + 1], hjr[kt][3]);
#pragma unroll
                for (int nt = 0; nt < 4; nt++) {
                    uint2 bw = *(const uint2*)&sW2f[((kt * 4 + nt) * 32 + lane) * 2];
                    asm volatile(
                        "mma.sync.aligned.m16n8k16.row.col.f32.bf16.bf16.f32 "
                        "{%0,%1,%2,%3}, {%4,%5,%6,%7}, {%8,%9}, {%0,%1,%2,%3};"
                        : "+f"(cr[nt][0]), "+f"(cr[nt][1]),
                          "+f"(cr[nt][2]), "+f"(cr[nt][3])
                        : "r"(a0), "r"(a1), "r"(a2), "r"(a3),
                          "r"(bw.x), "r"(bw.y));
                }
            }

            // Chained MMA2: h2 = relu(cr) packed bf16 (D1 layout == A2
            // layout); B = w3 dup; accumulator init = b3. s lands at c==0.
            float cr2[4] = {b3v, 0.f, b3v, 0.f};
#pragma unroll
            for (int kt2 = 0; kt2 < 2; kt2++) {
                uint32_t a0 = pk_relu(cr[kt2 * 2][0],     cr[kt2 * 2][1]);
                uint32_t a1 = pk_relu(cr[kt2 * 2][2],     cr[kt2 * 2][3]);
                uint32_t a2 = pk_relu(cr[kt2 * 2 + 1][0], cr[kt2 * 2 + 1][1]);
                uint32_t a3 = pk_relu(cr[kt2 * 2 + 1][2], cr[kt2 * 2 + 1][3]);
                asm volatile(
                    "mma.sync.aligned.m16n8k16.row.col.f32.bf16.bf16.f32 "
                    "{%0,%1,%2,%3}, {%4,%5,%6,%7}, {%8,%9}, {%0,%1,%2,%3};"
                    : "+f"(cr2[0]), "+f"(cr2[1]), "+f"(cr2[2]), "+f"(cr2[3])
                    : "r"(a0), "r"(a1), "r"(a2), "r"(a3),
                      "r"(w3f[kt2][0]), "r"(w3f[kt2][1]));
            }

            if (c == 0) {
                int j = j0 + jb;
                float v0 = (j > i) ? 1.f / (1.f + __expf(-cr2[0])) : 0.f;
                out[(size_t)i * n + j] = v0;
                int j8 = j + 8;
                float v1 = (j8 > i) ? 1.f / (1.f + __expf(-cr2[2])) : 0.f;
                out[(size_t)i * n + j8] = v1;
            }
        }
    }
}

// ---------------- launch ----------------------------------------------------
extern "C" void kernel_launch(void* const* d_in, const int* in_sizes, int n_in,
                              void* d_out, int out_size)
{
    const int*   si = (const int*)d_in[0];
    const int*   ri = (const int*)d_in[1];
    const int*   oi = (const int*)d_in[2];
    const float* st = (const float*)d_in[3];
    const float* rt = (const float*)d_in[4];
    const float* ot = (const float*)d_in[5];
    const float* pw = (const float*)d_in[6];
    const float* pb = (const float*)d_in[7];
    const float* w1 = (const float*)d_in[8];
    const float* b1 = (const float*)d_in[9];
    const float* w2 = (const float*)d_in[10];
    const float* b2 = (const float*)d_in[11];
    const float* w3 = (const float*)d_in[12];
    const float* b3 = (const float*)d_in[13];
    float* out = (float*)d_out;
    const int n = in_sizes[0];

    p1_kernel<<<(41 * ED * 32 + 255) / 256, 256>>>(st, rt, ot, pw);
    p2_kernel<<<(2 * 41 * ED * 32 + 255) / 256, 256>>>(pb, w1, b1);

    int total = n * (ED / 4);
    gather_kernel<<<(total + 255) / 256, 256>>>(si, ri, oi, n);

    dim3 grid(n / TJ, n / TI);
    score_kernel<<<grid, 256>>>(w2, b2, w3, b3, out, n);
}

// round 13
// speedup vs baseline: 4.7250x; 1.0501x over previous
#include <cuda_runtime.h>
#include <cuda_bf16.h>
#include <math.h>
#include <cstdint>

#define ED    64      // embed dim
#define NKK   32      // w2 output dim
#define N_MAX 2048

// ---------------- device scratch (no allocations allowed) ----------------
__device__ float g_P[41 * ED];      // projected tables (stage 1)
__device__ float g_Atab[41 * ED];
__device__ float g_Btab[41 * ED];
// Packed bf16x2 per-row features: [n][d/2] (lo half = even d)
__device__ uint32_t g_HIh[N_MAX * (ED / 2)];
__device__ uint32_t g_HJh[N_MAX * (ED / 2)];

#define BF16X2_ONE 0x3F803F80u

__device__ __forceinline__ float warp_sum(float v) {
#pragma unroll
    for (int s = 16; s; s >>= 1) v += __shfl_xor_sync(0xffffffffu, v, s);
    return v;
}

__device__ __forceinline__ uint32_t bf2(float lo, float hi) {
    uint32_t r;
    asm("cvt.rn.bf16x2.f32 %0, %1, %2;" : "=r"(r) : "f"(hi), "f"(lo));
    return r;
}
// fused a*1 + b with relu output (single instruction; add.relu rejected by
// this ptxas, fma.rn.relu is the documented fused form).
__device__ __forceinline__ uint32_t hadd2_relu(uint32_t a, uint32_t b) {
    uint32_t r;
    asm("fma.rn.relu.bf16x2 %0, %1, %2, %3;"
        : "=r"(r) : "r"(a), "r"(BF16X2_ONE), "r"(b));
    return r;
}
// fused pack two f32 -> bf16x2 with relu output (single instruction).
__device__ __forceinline__ uint32_t pk_relu(float lo, float hi) {
    uint32_t r;
    asm("cvt.rn.relu.bf16x2.f32 %0, %1, %2;" : "=r"(r) : "f"(hi), "f"(lo));
    return r;
}

// ---------------- stage P1: projected tables, one warp per output ----------
__global__ void p1_kernel(const float* __restrict__ st,
                          const float* __restrict__ rt,
                          const float* __restrict__ ot,
                          const float* __restrict__ pw)   // [64][192]
{
    int warp = (blockIdx.x * blockDim.x + threadIdx.x) >> 5;
    int lane = threadIdx.x & 31;
    if (warp >= 41 * ED) return;
    int row = warp >> 6, k = warp & 63;
    const float* tab;
    int off;
    if (row < 16)      { tab = st + row * ED;        off = 0;   }
    else if (row < 25) { tab = rt + (row - 16) * ED; off = 64;  }
    else               { tab = ot + (row - 25) * ED; off = 128; }
    const float* wrow = pw + k * 192 + off;
    float v = tab[lane] * wrow[lane] + tab[lane + 32] * wrow[lane + 32];
    v = warp_sum(v);
    if (lane == 0) g_P[warp] = v;
}

// ---------------- stage P2: A/B tables, one warp per output ----------------
__global__ void p2_kernel(const float* __restrict__ pb,   // [64]
                          const float* __restrict__ w1,   // [64][128]
                          const float* __restrict__ b1)   // [64]
{
    int warp = (blockIdx.x * blockDim.x + threadIdx.x) >> 5;
    int lane = threadIdx.x & 31;
    if (warp >= 2 * 41 * ED) return;
    int side = warp / (41 * ED);
    int rem  = warp % (41 * ED);
    int row = rem >> 6, d = rem & 63;
    const float* w1row = w1 + d * 128 + side * 64;
    const float* Prow  = g_P + row * ED;
    float v = Prow[lane] * w1row[lane] + Prow[lane + 32] * w1row[lane + 32];
    if (row >= 25)
        v += pb[lane] * w1row[lane] + pb[lane + 32] * w1row[lane + 32];
    v = warp_sum(v);
    if (lane == 0) {
        if (row >= 25 && side == 1) v += b1[d];
        if (side) g_Btab[rem] = v;
        else      g_Atab[rem] = v;
    }
}

// ---------------- gather -> HI/HJ packed bf16x2, [n][d/2] ------------------
__global__ void gather_kernel(const int* __restrict__ si,
                              const int* __restrict__ ri,
                              const int* __restrict__ oi, int n)
{
    int g = blockIdx.x * blockDim.x + threadIdx.x;
    if (g >= n * (ED / 4)) return;
    int nn = g >> 4;
    int c  = (g & 15) * 4;
    int s = si[nn], r = ri[nn], o = oi[nn];

    float4 a0 = *(const float4*)&g_Atab[s * ED + c];
    float4 a1 = *(const float4*)&g_Atab[(16 + r) * ED + c];
    float4 a2 = *(const float4*)&g_Atab[(25 + o) * ED + c];
    uint2 hi;
    hi.x = bf2(a0.x + a1.x + a2.x, a0.y + a1.y + a2.y);
    hi.y = bf2(a0.z + a1.z + a2.z, a0.w + a1.w + a2.w);
    *(uint2*)&g_HIh[nn * 32 + c / 2] = hi;

    float4 b0 = *(const float4*)&g_Btab[s * ED + c];
    float4 b1v = *(const float4*)&g_Btab[(16 + r) * ED + c];
    float4 b2v = *(const float4*)&g_Btab[(25 + o) * ED + c];
    uint2 hj;
    hj.x = bf2(b0.x + b1v.x + b2v.x, b0.y + b1v.y + b2v.y);
    hj.y = bf2(b0.z + b1v.z + b2v.z, b0.w + b1v.w + b2v.w);
    *(uint2*)&g_HJh[nn * 32 + c / 2] = hj;
}

// ---------------- score kernel: chained mma.sync bf16 ----------------------
// CTA tile = 64 i x 32 j. Warp w owns i-rows w*8..w*8+7. MMA1: 16 j-pairs x
// 32 k_out over d (b2 folded into accumulator init). MMA2 (chained): D1
// fragment relu'd/packed in-place (single cvt.rn.relu) becomes the A
// fragment of a second MMA vs a w3-duplicated B; b3 is the MMA2 init; the
// score lands in lanes c==0 with no shuffle.
// hi rows stored in SMEM pre-permuted to fragment order (pairs (d2, d2+4)
// adjacent) -> hir is 4 LDS.64. B fragments packed two-nt-wide -> 8 LDS.128.
#define TI 64
#define TJ 32
#define SJ2 40  // hjT2 row stride (words): bank = 8c+gr, conflict-free
#define SHI 34  // sHIh row stride (words): even (8B align), bank-staggered

__global__ void __launch_bounds__(256, 3)
score_kernel(const float* __restrict__ w2,   // [32][64]
             const float* __restrict__ b2,   // [32]
             const float* __restrict__ w3,   // [1][32]
             const float* __restrict__ b3,   // [1]
             float* __restrict__ out, int n)
{
    const int t = threadIdx.x, w = t >> 5, lane = t & 31;
    const int gr = lane >> 2, c = lane & 3;
    const int i0 = blockIdx.y * TI, j0 = blockIdx.x * TJ;

    // Tile entirely at/below diagonal -> pure zeros.
    if (j0 + TJ - 1 <= i0) {
        const float4 z = make_float4(0.f, 0.f, 0.f, 0.f);
#pragma unroll
        for (int q = 0; q < 2; q++) {
            int idx = q * 256 + t;
            int r = idx >> 3, f4 = (idx & 7) * 4;
            *(float4*)&out[(size_t)(i0 + r) * n + j0 + f4] = z;
        }
        return;
    }

    __shared__ __align__(16) uint32_t sHIh[TI * SHI];     // permuted, 8.5KB
    __shared__ uint32_t sHJT2[32 * SJ2];                  // [d2][j], 5KB
    // B fragments, uint4 per (kt, ntp, lane): (nt r0, nt r1, nt+1 r0, nt+1 r1)
    __shared__ __align__(16) uint32_t sW2f4[4 * 2 * 32 * 4];  // 4KB

    // Stage hi rows, permuting word w -> pos = kt*8 + cc*2 + rr
    // (w = kt*8 + cc + 4*rr). Fragment pair (d2, d2+4) becomes adjacent.
#pragma unroll
    for (int q = 0; q < 2; q++) {
        int idx = q * 256 + t;
        int r = idx >> 3, w4 = (idx & 7) * 4;     // words w4..w4+3: same kt,rr
        uint4 v = *(const uint4*)&g_HIh[(i0 + r) * 32 + w4];
        int kt = w4 >> 3, rr = (w4 >> 2) & 1;
        uint32_t* dst = &sHIh[r * SHI + kt * 8 + rr];
        dst[0] = v.x; dst[2] = v.y; dst[4] = v.z; dst[6] = v.w;
    }
    // Stage hj transposed: sHJT2[d2][j] = packed hj(j0+j, 2*d2, 2*d2+1).
    {
        int j = t & 31, dg = t >> 5;           // dg*4 .. dg*4+3 d2-words
        uint4 v = *(const uint4*)&g_HJh[(j0 + j) * 32 + dg * 4];
        sHJT2[(dg * 4 + 0) * SJ2 + j] = v.x;
        sHJT2[(dg * 4 + 1) * SJ2 + j] = v.y;
        sHJT2[(dg * 4 + 2) * SJ2 + j] = v.z;
        sHJT2[(dg * 4 + 3) * SJ2 + j] = v.w;
    }
    // Stage B fragments (one uint4 per thread): kt = t>>6, ntp = (t>>5)&1.
    {
        int kt = t >> 6, ntp = (t >> 5) & 1, ln = t & 31;
        int col  = kt * 16 + 2 * (ln & 3);
        int row0 = (ntp * 2) * 8 + (ln >> 2);
        const float* wr0 = w2 + row0 * ED + col;
        const float* wr1 = wr0 + 8 * ED;       // row0 + 8 = next nt
        uint4 v;
        v.x = bf2(wr0[0], wr0[1]); v.y = bf2(wr0[8], wr0[9]);
        v.z = bf2(wr1[0], wr1[1]); v.w = bf2(wr1[8], wr1[9]);
        *(uint4*)&sW2f4[((kt * 2 + ntp) * 32 + ln) * 4] = v;
    }
    // MMA1 accumulator init values (= b2 for cols nt*8 + 2c, +1).
    float b2v[8];
#pragma unroll
    for (int nt = 0; nt < 4; nt++) {
        float2 bb = *(const float2*)&b2[nt * 8 + 2 * c];
        b2v[nt * 2] = bb.x; b2v[nt * 2 + 1] = bb.y;
    }
    // MMA2 B fragments: w3 duplicated across all N-columns (no gr term).
    uint32_t w3f[2][2];
#pragma unroll
    for (int kt2 = 0; kt2 < 2; kt2++) {
        const float* wr = w3 + kt2 * 16 + 2 * c;
        w3f[kt2][0] = bf2(wr[0], wr[1]);
        w3f[kt2][1] = bf2(wr[8], wr[9]);
    }
    const float b3v = b3[0];
    __syncthreads();

#pragma unroll
    for (int jt = 0; jt < 2; jt++) {
        const int jb = jt * 16 + gr;
        // hj fragments for this jt, all kt: cached across the il loop.
        uint32_t hjr[4][4];
#pragma unroll
        for (int kt = 0; kt < 4; kt++) {
            const int d2a = kt * 8 + c;
            hjr[kt][0] = sHJT2[d2a * SJ2 + jb];
            hjr[kt][1] = sHJT2[d2a * SJ2 + jb + 8];
            hjr[kt][2] = sHJT2[(d2a + 4) * SJ2 + jb];
            hjr[kt][3] = sHJT2[(d2a + 4) * SJ2 + jb + 8];
        }
#pragma unroll 1
        for (int il = 0; il < 8; il++) {
            const int i = i0 + w * 8 + il;
            const uint32_t* hiRow = sHIh + (w * 8 + il) * SHI;
            uint2 hirp[4];
#pragma unroll
            for (int kt = 0; kt < 4; kt++)
                hirp[kt] = *(const uint2*)&hiRow[kt * 8 + c * 2];
            // MMA1 accumulators init = b2 (bias folded in).
            float cr[4][4];
#pragma unroll
            for (int nt = 0; nt < 4; nt++) {
                cr[nt][0] = b2v[nt * 2]; cr[nt][1] = b2v[nt * 2 + 1];
                cr[nt][2] = b2v[nt * 2]; cr[nt][3] = b2v[nt * 2 + 1];
            }

#pragma unroll
            for (int kt = 0; kt < 4; kt++) {
                uint32_t a0 = hadd2_relu(hirp[kt].x, hjr[kt][0]);
                uint32_t a1 = hadd2_relu(hirp[kt].x, hjr[kt][1]);
                uint32_t a2 = hadd2_relu(hirp[kt].y, hjr[kt][2]);
                uint32_t a3 = hadd2_relu(hirp[kt].y, hjr[kt][3]);
#pragma unroll
                for (int ntp = 0; ntp < 2; ntp++) {
                    uint4 bw = *(const uint4*)
                        &sW2f4[((kt * 2 + ntp) * 32 + lane) * 4];
                    asm volatile(
                        "mma.sync.aligned.m16n8k16.row.col.f32.bf16.bf16.f32 "
                        "{%0,%1,%2,%3}, {%4,%5,%6,%7}, {%8,%9}, {%0,%1,%2,%3};"
                        : "+f"(cr[ntp * 2][0]), "+f"(cr[ntp * 2][1]),
                          "+f"(cr[ntp * 2][2]), "+f"(cr[ntp * 2][3])
                        : "r"(a0), "r"(a1), "r"(a2), "r"(a3),
                          "r"(bw.x), "r"(bw.y));
                    asm volatile(
                        "mma.sync.aligned.m16n8k16.row.col.f32.bf16.bf16.f32 "
                        "{%0,%1,%2,%3}, {%4,%5,%6,%7}, {%8,%9}, {%0,%1,%2,%3};"
                        : "+f"(cr[ntp * 2 + 1][0]), "+f"(cr[ntp * 2 + 1][1]),
                          "+f"(cr[ntp * 2 + 1][2]), "+f"(cr[ntp * 2 + 1][3])
                        : "r"(a0), "r"(a1), "r"(a2), "r"(a3),
                          "r"(bw.z), "r"(bw.w));
                }
            }

            // Chained MMA2: h2 = relu(cr) packed bf16 (D1 layout == A2
            // layout); B = w3 dup; accumulator init = b3. s lands at c==0.
            float cr2[4] = {b3v, 0.f, b3v, 0.f};
#pragma unroll
            for (int kt2 = 0; kt2 < 2; kt2++) {
                uint32_t a0 = pk_relu(cr[kt2 * 2][0],     cr[kt2 * 2][1]);
                uint32_t a1 = pk_relu(cr[kt2 * 2][2],     cr[kt2 * 2][3]);
                uint32_t a2 = pk_relu(cr[kt2 * 2 + 1][0], cr[kt2 * 2 + 1][1]);
                uint32_t a3 = pk_relu(cr[kt2 * 2 + 1][2], cr[kt2 * 2 + 1][3]);
                asm volatile(
                    "mma.sync.aligned.m16n8k16.row.col.f32.bf16.bf16.f32 "
                    "{%0,%1,%2,%3}, {%4,%5,%6,%7}, {%8,%9}, {%0,%1,%2,%3};"
                    : "+f"(cr2[0]), "+f"(cr2[1]), "+f"(cr2[2]), "+f"(cr2[3])
                    : "r"(a0), "r"(a1), "r"(a2), "r"(a3),
                      "r"(w3f[kt2][0]), "r"(w3f[kt2][1]));
            }

            if (c == 0) {
                int j = j0 + jb;
                float v0 = (j > i) ? 1.f / (1.f + __expf(-cr2[0])) : 0.f;
                out[(size_t)i * n + j] = v0;
                int j8 = j + 8;
                float v1 = (j8 > i) ? 1.f / (1.f + __expf(-cr2[2])) : 0.f;
                out[(size_t)i * n + j8] = v1;
            }
        }
    }
}

// ---------------- launch ----------------------------------------------------
extern "C" void kernel_launch(void* const* d_in, const int* in_sizes, int n_in,
                              void* d_out, int out_size)
{
    const int*   si = (const int*)d_in[0];
    const int*   ri = (const int*)d_in[1];
    const int*   oi = (const int*)d_in[2];
    const float* st = (const float*)d_in[3];
    const float* rt = (const float*)d_in[4];
    const float* ot = (const float*)d_in[5];
    const float* pw = (const float*)d_in[6];
    const float* pb = (const float*)d_in[7];
    const float* w1 = (const float*)d_in[8];
    const float* b1 = (const float*)d_in[9];
    const float* w2 = (const float*)d_in[10];
    const float* b2 = (const float*)d_in[11];
    const float* w3 = (const float*)d_in[12];
    const float* b3 = (const float*)d_in[13];
    float* out = (float*)d_out;
    const int n = in_sizes[0];

    p1_kernel<<<(41 * ED * 32 + 255) / 256, 256>>>(st, rt, ot, pw);
    p2_kernel<<<(2 * 41 * ED * 32 + 255) / 256, 256>>>(pb, w1, b1);

    int total = n * (ED / 4);
    gather_kernel<<<(total + 255) / 256, 256>>>(si, ri, oi, n);

    dim3 grid(n / TJ, n / TI);
    score_kernel<<<grid, 256>>>(w2, b2, w3, b3, out, n);
}